// round 15
// baseline (speedup 1.0000x reference)
#include <cuda_runtime.h>
#include <math.h>

#define N_ATOMS 20000
#define N_EDGES 640000
#define FDIM    128
#define F3      (3 * FDIM)      // 384
#define N_RADIAL 20
#define CUTOFF  5.0f
#define PI_F    3.14159265358979323846f

typedef unsigned long long u64;

// ---------------- scratch (static device globals; no runtime allocs) -------
__device__ float  g_x[(size_t)N_ATOMS * F3];   // node context [N,3F]
__device__ int    g_count[N_ATOMS];
__device__ int2   g_range[N_ATOMS];            // per-node (beg, end)
__device__ int    g_cursor[N_ATOMS];
__device__ float4 g_rec[N_EDGES];              // slot -> (ex, ey, ez, j-as-int)

// ---------------- f32x2 packed helpers -------------------------------------
__device__ __forceinline__ u64 pack2(float x, float y) {
    u64 r; asm("mov.b64 %0, {%1,%2};" : "=l"(r) : "f"(x), "f"(y)); return r;
}
__device__ __forceinline__ void unpack2(u64 v, float& x, float& y) {
    asm("mov.b64 {%0,%1}, %2;" : "=f"(x), "=f"(y) : "l"(v));
}
__device__ __forceinline__ void fma2(u64& d, u64 a, u64 b) {
    asm("fma.rn.f32x2 %0, %1, %2, %0;" : "+l"(d) : "l"(a), "l"(b));
}

// ---------------------------------------------------------------------------
// Kernel 1: node MLP, scalar FFMA, LDS.128 k-unroll, 16 rows / 256 threads,
// register double-buffered weight prefetch (measured ~106us).
// ---------------------------------------------------------------------------
#define MROWS 16

__global__ __launch_bounds__(256)
void mlp_kernel(const float* __restrict__ q,
                const float* __restrict__ W1, const float* __restrict__ b1,
                const float* __restrict__ W2, const float* __restrict__ b2,
                float* __restrict__ x)
{
    __shared__ float qs[MROWS][FDIM];   // 8 KB, k fastest (float4-able)
    __shared__ float hs[MROWS][FDIM];   // 8 KB

    const int f    = threadIdx.x & 127;
    const int half = threadIdx.x >> 7;       // 0/1
    const int r0   = half * 8;                // local row base (8 rows/half)
    const int row0 = blockIdx.x * MROWS;

    for (int idx = threadIdx.x; idx < MROWS * FDIM; idx += 256)
        qs[idx >> 7][idx & 127] = q[(size_t)row0 * FDIM + idx];
    __syncthreads();

    // stage 1: h = silu(q @ W1 + b1)
    {
        float acc[8];
        const float bb = b1[f];
        #pragma unroll
        for (int r = 0; r < 8; r++) acc[r] = bb;

        float w0 = W1[0 * FDIM + f];
        float w1 = W1[1 * FDIM + f];
        float w2 = W1[2 * FDIM + f];
        float w3 = W1[3 * FDIM + f];

        for (int k = 0; k < FDIM; k += 4) {
            const int kn = (k + 4) & (FDIM - 1);   // wraps to 0 on last tile
            const float n0 = W1[(kn + 0) * FDIM + f];
            const float n1 = W1[(kn + 1) * FDIM + f];
            const float n2 = W1[(kn + 2) * FDIM + f];
            const float n3 = W1[(kn + 3) * FDIM + f];
            #pragma unroll
            for (int r = 0; r < 8; r++) {
                const float4 qv = *(const float4*)&qs[r0 + r][k];  // LDS.128 bcast
                acc[r] = fmaf(qv.x, w0, acc[r]);
                acc[r] = fmaf(qv.y, w1, acc[r]);
                acc[r] = fmaf(qv.z, w2, acc[r]);
                acc[r] = fmaf(qv.w, w3, acc[r]);
            }
            w0 = n0; w1 = n1; w2 = n2; w3 = n3;
        }
        #pragma unroll
        for (int r = 0; r < 8; r++) {
            const float v = acc[r];
            hs[r0 + r][f] = v / (1.0f + __expf(-v));
        }
    }
    __syncthreads();

    // stage 2: x = h @ W2 + b2
    {
        float a0[8], a1[8], a2[8];
        const float c0 = b2[f], c1 = b2[FDIM + f], c2 = b2[2 * FDIM + f];
        #pragma unroll
        for (int r = 0; r < 8; r++) { a0[r] = c0; a1[r] = c1; a2[r] = c2; }

        float wa[4], wb[4], wc[4];
        #pragma unroll
        for (int u = 0; u < 4; u++) {
            wa[u] = W2[u * F3 + f];
            wb[u] = W2[u * F3 + FDIM + f];
            wc[u] = W2[u * F3 + 2 * FDIM + f];
        }

        for (int k = 0; k < FDIM; k += 4) {
            const int kn = (k + 4) & (FDIM - 1);   // wraps to 0 on last tile
            float na[4], nb[4], nc[4];
            #pragma unroll
            for (int u = 0; u < 4; u++) {
                na[u] = W2[(kn + u) * F3 + f];
                nb[u] = W2[(kn + u) * F3 + FDIM + f];
                nc[u] = W2[(kn + u) * F3 + 2 * FDIM + f];
            }
            #pragma unroll
            for (int r = 0; r < 8; r++) {
                const float4 hv = *(const float4*)&hs[r0 + r][k];  // LDS.128 bcast
                a0[r] = fmaf(hv.x, wa[0], a0[r]);
                a0[r] = fmaf(hv.y, wa[1], a0[r]);
                a0[r] = fmaf(hv.z, wa[2], a0[r]);
                a0[r] = fmaf(hv.w, wa[3], a0[r]);
                a1[r] = fmaf(hv.x, wb[0], a1[r]);
                a1[r] = fmaf(hv.y, wb[1], a1[r]);
                a1[r] = fmaf(hv.z, wb[2], a1[r]);
                a1[r] = fmaf(hv.w, wb[3], a1[r]);
                a2[r] = fmaf(hv.x, wc[0], a2[r]);
                a2[r] = fmaf(hv.y, wc[1], a2[r]);
                a2[r] = fmaf(hv.z, wc[2], a2[r]);
                a2[r] = fmaf(hv.w, wc[3], a2[r]);
            }
            #pragma unroll
            for (int u = 0; u < 4; u++) { wa[u] = na[u]; wb[u] = nb[u]; wc[u] = nc[u]; }
        }
        #pragma unroll
        for (int r = 0; r < 8; r++) {
            const size_t base = (size_t)(row0 + r0 + r) * F3;
            x[base + f]            = a0[r];
            x[base + FDIM + f]     = a1[r];
            x[base + 2 * FDIM + f] = a2[r];
        }
    }
}

// ---------------------------------------------------------------------------
// CSR construction: memset -> histogram -> scan -> scatter (float4 records)
// ---------------------------------------------------------------------------
__global__ void hist_kernel(const int* __restrict__ edge_index)
{
    int e = blockIdx.x * blockDim.x + threadIdx.x;
    if (e < N_EDGES) atomicAdd(&g_count[edge_index[e]], 1);
}

__global__ __launch_bounds__(1024)
void scan_kernel()
{
    __shared__ int warp_sums[32];
    __shared__ int chunk_carry;
    const int tid  = threadIdx.x;
    const int lane = tid & 31;
    const int wid  = tid >> 5;
    if (tid == 0) chunk_carry = 0;
    __syncthreads();

    const int nchunks = (N_ATOMS + 1023) / 1024;
    for (int c = 0; c < nchunks; c++) {
        int idx = c * 1024 + tid;
        int v = (idx < N_ATOMS) ? g_count[idx] : 0;
        int s = v;
        #pragma unroll
        for (int o = 1; o < 32; o <<= 1) {
            int t = __shfl_up_sync(0xffffffffu, s, o);
            if (lane >= o) s += t;
        }
        if (lane == 31) warp_sums[wid] = s;
        __syncthreads();
        if (wid == 0) {
            int ws = warp_sums[lane];
            #pragma unroll
            for (int o = 1; o < 32; o <<= 1) {
                int t = __shfl_up_sync(0xffffffffu, ws, o);
                if (lane >= o) ws += t;
            }
            warp_sums[lane] = ws;
        }
        __syncthreads();
        int warp_off = (wid > 0) ? warp_sums[wid - 1] : 0;
        int excl = chunk_carry + warp_off + s - v;
        if (idx < N_ATOMS) {
            g_range[idx]  = make_int2(excl, excl + v);   // (beg, end)
            g_cursor[idx] = excl;
        }
        __syncthreads();
        if (tid == 1023) chunk_carry += warp_off + s;
    }
}

// writes a self-contained 16B record per edge: (ex, ey, ez, j)
__global__ void scatter_kernel(const int* __restrict__ edge_index,
                               const float* __restrict__ ew)
{
    int e = blockIdx.x * blockDim.x + threadIdx.x;
    if (e < N_EDGES) {
        const int i = edge_index[e];
        const int j = edge_index[N_EDGES + e];
        const float ex = ew[3 * e + 0];     // coalesced (e sequential)
        const float ey = ew[3 * e + 1];
        const float ez = ew[3 * e + 2];
        int pos = atomicAdd(&g_cursor[i], 1);
        g_rec[pos] = make_float4(ex, ey, ez, __int_as_float(j));
    }
}

// ---------------------------------------------------------------------------
// Kernel 2 (fused): per-node accumulation -- PROVEN R12 CONFIGURATION (458us).
// Block = one node, 128 threads.  LDS.64 dup-pair matvec + distance-1 gather
// pipeline.  (distance-2, LDS.128, and persistence variants all proven slower.)
// ---------------------------------------------------------------------------
#define CHUNK 64
#define RECW  46    // 4 scalars + 20 duplicated pairs (44), padded to even 46

__global__ __launch_bounds__(128)
void node_kernel(const float* __restrict__ q,
                 const float* __restrict__ mu,
                 const float* __restrict__ Wf,
                 const float* __restrict__ bf,
                 float* __restrict__ qout,
                 float* __restrict__ muout)
{
    __shared__ float srec[CHUNK][RECW];   // 11776 B
    __shared__ int   sj[CHUNK];

    const int i = blockIdx.x;
    const int c = threadIdx.x;

    // Wf slices in registers (identical across blocks -> L1-hot broadcast)
    u64   wqr[N_RADIAL];
    float wm[N_RADIAL];
    #pragma unroll
    for (int r = 0; r < N_RADIAL; r++) {
        wqr[r] = pack2(Wf[r * F3 + c], Wf[r * F3 + FDIM + c]);
        wm[r]  = Wf[r * F3 + 2 * FDIM + c];
    }
    const float bq = bf[c], bR = bf[FDIM + c], bm = bf[2 * FDIM + c];

    const int2 range = g_range[i];
    const int beg = range.x;
    const int end = range.y;

    float aq = 0.0f, a0 = 0.0f, a1 = 0.0f, a2 = 0.0f;

    for (int base = beg; base < end; base += CHUNK) {
        const int m = min(CHUNK, end - base);

        __syncthreads();   // previous chunk fully consumed before overwrite
        if (c < m) {
            const float4 rec = g_rec[base + c];   // one coalesced LDG.128
            sj[c] = __float_as_int(rec.w);

            const float ex = rec.x;
            const float ey = rec.y;
            const float ez = rec.z;
            const float dd = fmaf(ex, ex, fmaf(ey, ey, ez * ez));
            const float rd = rsqrtf(dd);
            const float d  = dd * rd;

            float s1, c1;
            __sincosf(d * (PI_F / CUTOFF), &s1, &c1);
            float env = 0.5f * (c1 + 1.0f);
            env = (d < CUTOFF) ? env : 0.0f;

            float* row = srec[c];
            row[0] = ex * rd;
            row[1] = ey * rd;
            row[2] = ez * rd;
            row[3] = env;

            const float re    = rd * env;
            const float two_c = 2.0f * c1;
            float sm1 = 0.0f, sn = s1;
            #pragma unroll
            for (int n = 0; n < N_RADIAL; n++) {
                const float b = sn * re;
                *(float2*)&row[4 + 2 * n] = make_float2(b, b);  // dup pair, STS.64
                const float nx = two_c * sn - sm1;
                sm1 = sn; sn = nx;
            }
        }
        __syncthreads();

        // distance-1 software-pipelined gathers (proven R12 form)
        {
            int j0 = sj[0];
            const float* xr = g_x + (size_t)j0 * F3;
            const float* mr = mu  + (size_t)j0 * F3;
            float x0 = xr[c], x1 = xr[FDIM + c], x2 = xr[2 * FDIM + c];
            float m0 = mr[c], m1 = mr[FDIM + c], m2 = mr[2 * FDIM + c];

            #pragma unroll 2
            for (int t = 0; t < m; t++) {
                const int tn = min(t + 1, m - 1);
                const int jn = sj[tn];
                const float* xrn = g_x + (size_t)jn * F3;
                const float* mrn = mu  + (size_t)jn * F3;
                const float nx0 = xrn[c];
                const float nx1 = xrn[FDIM + c];
                const float nx2 = xrn[2 * FDIM + c];
                const float nm0 = mrn[c];
                const float nm1 = mrn[FDIM + c];
                const float nm2 = mrn[2 * FDIM + c];

                const float d0  = srec[t][0];
                const float d1  = srec[t][1];
                const float d2  = srec[t][2];
                const float env = srec[t][3];

                u64   fqr = pack2(bq * env, bR * env);
                float fm  = bm * env;
                #pragma unroll
                for (int r = 0; r < N_RADIAL; r++) {
                    const float2 b2v = *(const float2*)&srec[t][4 + 2 * r];  // LDS.64
                    fma2(fqr, pack2(b2v.x, b2v.y), wqr[r]);
                    fm = fmaf(b2v.x, wm[r], fm);
                }
                float fq, fR; unpack2(fqr, fq, fR);

                aq = fmaf(fq, x0, aq);
                const float dR = fR * x1;
                const float dm = fm * x2;
                a0 = fmaf(dR, d0, fmaf(dm, m0, a0));
                a1 = fmaf(dR, d1, fmaf(dm, m1, a1));
                a2 = fmaf(dR, d2, fmaf(dm, m2, a2));

                x0 = nx0; x1 = nx1; x2 = nx2;
                m0 = nm0; m1 = nm1; m2 = nm2;
            }
        }
    }

    qout[(size_t)i * FDIM + c] = q[(size_t)i * FDIM + c] + aq;
    float* mo = muout + (size_t)i * F3;
    const float* mi = mu + (size_t)i * F3;
    mo[c]            = mi[c]            + a0;
    mo[FDIM + c]     = mi[FDIM + c]     + a1;
    mo[2 * FDIM + c] = mi[2 * FDIM + c] + a2;
}

// ---------------------------------------------------------------------------
extern "C" void kernel_launch(void* const* d_in, const int* in_sizes, int n_in,
                              void* d_out, int out_size)
{
    const float* q   = (const float*)d_in[0];
    const float* mu  = (const float*)d_in[1];
    const int*   ei  = (const int*)  d_in[2];
    const float* ew  = (const float*)d_in[3];
    const float* W1  = (const float*)d_in[4];
    const float* b1  = (const float*)d_in[5];
    const float* W2  = (const float*)d_in[6];
    const float* b2  = (const float*)d_in[7];
    const float* Wf  = (const float*)d_in[8];
    const float* bf  = (const float*)d_in[9];

    float* out   = (float*)d_out;
    float* qout  = out;                                   // [N, F]
    float* muout = out + (size_t)N_ATOMS * FDIM;          // [N, 3, F]

    float* fx; cudaGetSymbolAddress((void**)&fx, g_x);
    int*   fc; cudaGetSymbolAddress((void**)&fc, g_count);

    // one-time-safe attribute: maximize L1 carveout for the weight-streaming
    // MLP (16KB smem used; rest of the 228KB unified cache -> L1D).
    cudaFuncSetAttribute(mlp_kernel,
                         cudaFuncAttributePreferredSharedMemoryCarveout, 10);

    // fork: MLP runs on a side stream, concurrent with the CSR chain.
    cudaStream_t s2;
    cudaStreamCreateWithFlags(&s2, cudaStreamNonBlocking);
    cudaEvent_t ev_fork, ev_join;
    cudaEventCreateWithFlags(&ev_fork, cudaEventDisableTiming);
    cudaEventCreateWithFlags(&ev_join, cudaEventDisableTiming);

    cudaEventRecord(ev_fork, 0);
    cudaStreamWaitEvent(s2, ev_fork, 0);
    mlp_kernel<<<N_ATOMS / MROWS, 256, 0, s2>>>(q, W1, b1, W2, b2, fx);
    cudaEventRecord(ev_join, s2);

    // CSR build on the main stream (destination-grouped edge records)
    cudaMemsetAsync(fc, 0, N_ATOMS * sizeof(int), 0);
    hist_kernel<<<N_EDGES / 256, 256>>>(ei);
    scan_kernel<<<1, 1024>>>();
    scatter_kernel<<<N_EDGES / 256, 256>>>(ei, ew);

    // join: node kernel needs both g_x (MLP) and the CSR records
    cudaStreamWaitEvent(0, ev_join, 0);
    node_kernel<<<N_ATOMS, 128>>>(q, mu, Wf, bf, qout, muout);
}

// round 16
// speedup vs baseline: 1.2448x; 1.2448x over previous
#include <cuda_runtime.h>
#include <math.h>

#define N_ATOMS 20000
#define N_EDGES 640000
#define FDIM    128
#define F3      (3 * FDIM)      // 384
#define N_RADIAL 20
#define CUTOFF  5.0f
#define PI_F    3.14159265358979323846f

typedef unsigned long long u64;

// ---------------- scratch (static device globals; no runtime allocs) -------
__device__ float  g_x[(size_t)N_ATOMS * F3];   // node context [N,3F]
__device__ int    g_count[N_ATOMS];
__device__ int2   g_range[N_ATOMS];            // per-node (beg, end)
__device__ int    g_cursor[N_ATOMS];
__device__ float4 g_rec[N_EDGES];              // slot -> (ex, ey, ez, j-as-int)

// ---------------- f32x2 packed helpers -------------------------------------
__device__ __forceinline__ u64 pack2(float x, float y) {
    u64 r; asm("mov.b64 %0, {%1,%2};" : "=l"(r) : "f"(x), "f"(y)); return r;
}
__device__ __forceinline__ void unpack2(u64 v, float& x, float& y) {
    asm("mov.b64 {%0,%1}, %2;" : "=f"(x), "=f"(y) : "l"(v));
}
__device__ __forceinline__ void fma2(u64& d, u64 a, u64 b) {
    asm("fma.rn.f32x2 %0, %1, %2, %0;" : "+l"(d) : "l"(a), "l"(b));
}

// ---------------------------------------------------------------------------
// Kernel 1: node MLP, scalar FFMA, LDS.128 k-unroll, 16 rows / 256 threads,
// register double-buffered weight prefetch (measured ~106us).
// NOTE: no cache-carveout attributes -- per-kernel carveout switching inside
// a captured graph forces SM reconfiguration per replay (R15: +106us).
// ---------------------------------------------------------------------------
#define MROWS 16

__global__ __launch_bounds__(256)
void mlp_kernel(const float* __restrict__ q,
                const float* __restrict__ W1, const float* __restrict__ b1,
                const float* __restrict__ W2, const float* __restrict__ b2,
                float* __restrict__ x)
{
    __shared__ float qs[MROWS][FDIM];   // 8 KB, k fastest (float4-able)
    __shared__ float hs[MROWS][FDIM];   // 8 KB

    const int f    = threadIdx.x & 127;
    const int half = threadIdx.x >> 7;       // 0/1
    const int r0   = half * 8;                // local row base (8 rows/half)
    const int row0 = blockIdx.x * MROWS;

    for (int idx = threadIdx.x; idx < MROWS * FDIM; idx += 256)
        qs[idx >> 7][idx & 127] = q[(size_t)row0 * FDIM + idx];
    __syncthreads();

    // stage 1: h = silu(q @ W1 + b1)
    {
        float acc[8];
        const float bb = b1[f];
        #pragma unroll
        for (int r = 0; r < 8; r++) acc[r] = bb;

        float w0 = W1[0 * FDIM + f];
        float w1 = W1[1 * FDIM + f];
        float w2 = W1[2 * FDIM + f];
        float w3 = W1[3 * FDIM + f];

        for (int k = 0; k < FDIM; k += 4) {
            const int kn = (k + 4) & (FDIM - 1);   // wraps to 0 on last tile
            const float n0 = W1[(kn + 0) * FDIM + f];
            const float n1 = W1[(kn + 1) * FDIM + f];
            const float n2 = W1[(kn + 2) * FDIM + f];
            const float n3 = W1[(kn + 3) * FDIM + f];
            #pragma unroll
            for (int r = 0; r < 8; r++) {
                const float4 qv = *(const float4*)&qs[r0 + r][k];  // LDS.128 bcast
                acc[r] = fmaf(qv.x, w0, acc[r]);
                acc[r] = fmaf(qv.y, w1, acc[r]);
                acc[r] = fmaf(qv.z, w2, acc[r]);
                acc[r] = fmaf(qv.w, w3, acc[r]);
            }
            w0 = n0; w1 = n1; w2 = n2; w3 = n3;
        }
        #pragma unroll
        for (int r = 0; r < 8; r++) {
            const float v = acc[r];
            hs[r0 + r][f] = v / (1.0f + __expf(-v));
        }
    }
    __syncthreads();

    // stage 2: x = h @ W2 + b2
    {
        float a0[8], a1[8], a2[8];
        const float c0 = b2[f], c1 = b2[FDIM + f], c2 = b2[2 * FDIM + f];
        #pragma unroll
        for (int r = 0; r < 8; r++) { a0[r] = c0; a1[r] = c1; a2[r] = c2; }

        float wa[4], wb[4], wc[4];
        #pragma unroll
        for (int u = 0; u < 4; u++) {
            wa[u] = W2[u * F3 + f];
            wb[u] = W2[u * F3 + FDIM + f];
            wc[u] = W2[u * F3 + 2 * FDIM + f];
        }

        for (int k = 0; k < FDIM; k += 4) {
            const int kn = (k + 4) & (FDIM - 1);   // wraps to 0 on last tile
            float na[4], nb[4], nc[4];
            #pragma unroll
            for (int u = 0; u < 4; u++) {
                na[u] = W2[(kn + u) * F3 + f];
                nb[u] = W2[(kn + u) * F3 + FDIM + f];
                nc[u] = W2[(kn + u) * F3 + 2 * FDIM + f];
            }
            #pragma unroll
            for (int r = 0; r < 8; r++) {
                const float4 hv = *(const float4*)&hs[r0 + r][k];  // LDS.128 bcast
                a0[r] = fmaf(hv.x, wa[0], a0[r]);
                a0[r] = fmaf(hv.y, wa[1], a0[r]);
                a0[r] = fmaf(hv.z, wa[2], a0[r]);
                a0[r] = fmaf(hv.w, wa[3], a0[r]);
                a1[r] = fmaf(hv.x, wb[0], a1[r]);
                a1[r] = fmaf(hv.y, wb[1], a1[r]);
                a1[r] = fmaf(hv.z, wb[2], a1[r]);
                a1[r] = fmaf(hv.w, wb[3], a1[r]);
                a2[r] = fmaf(hv.x, wc[0], a2[r]);
                a2[r] = fmaf(hv.y, wc[1], a2[r]);
                a2[r] = fmaf(hv.z, wc[2], a2[r]);
                a2[r] = fmaf(hv.w, wc[3], a2[r]);
            }
            #pragma unroll
            for (int u = 0; u < 4; u++) { wa[u] = na[u]; wb[u] = nb[u]; wc[u] = nc[u]; }
        }
        #pragma unroll
        for (int r = 0; r < 8; r++) {
            const size_t base = (size_t)(row0 + r0 + r) * F3;
            x[base + f]            = a0[r];
            x[base + FDIM + f]     = a1[r];
            x[base + 2 * FDIM + f] = a2[r];
        }
    }
}

// ---------------------------------------------------------------------------
// CSR construction: memset -> histogram -> scan -> scatter (float4 records)
// ---------------------------------------------------------------------------
__global__ void hist_kernel(const int* __restrict__ edge_index)
{
    int e = blockIdx.x * blockDim.x + threadIdx.x;
    if (e < N_EDGES) atomicAdd(&g_count[edge_index[e]], 1);
}

__global__ __launch_bounds__(1024)
void scan_kernel()
{
    __shared__ int warp_sums[32];
    __shared__ int chunk_carry;
    const int tid  = threadIdx.x;
    const int lane = tid & 31;
    const int wid  = tid >> 5;
    if (tid == 0) chunk_carry = 0;
    __syncthreads();

    const int nchunks = (N_ATOMS + 1023) / 1024;
    for (int c = 0; c < nchunks; c++) {
        int idx = c * 1024 + tid;
        int v = (idx < N_ATOMS) ? g_count[idx] : 0;
        int s = v;
        #pragma unroll
        for (int o = 1; o < 32; o <<= 1) {
            int t = __shfl_up_sync(0xffffffffu, s, o);
            if (lane >= o) s += t;
        }
        if (lane == 31) warp_sums[wid] = s;
        __syncthreads();
        if (wid == 0) {
            int ws = warp_sums[lane];
            #pragma unroll
            for (int o = 1; o < 32; o <<= 1) {
                int t = __shfl_up_sync(0xffffffffu, ws, o);
                if (lane >= o) ws += t;
            }
            warp_sums[lane] = ws;
        }
        __syncthreads();
        int warp_off = (wid > 0) ? warp_sums[wid - 1] : 0;
        int excl = chunk_carry + warp_off + s - v;
        if (idx < N_ATOMS) {
            g_range[idx]  = make_int2(excl, excl + v);   // (beg, end)
            g_cursor[idx] = excl;
        }
        __syncthreads();
        if (tid == 1023) chunk_carry += warp_off + s;
    }
}

// writes a self-contained 16B record per edge: (ex, ey, ez, j)
__global__ void scatter_kernel(const int* __restrict__ edge_index,
                               const float* __restrict__ ew)
{
    int e = blockIdx.x * blockDim.x + threadIdx.x;
    if (e < N_EDGES) {
        const int i = edge_index[e];
        const int j = edge_index[N_EDGES + e];
        const float ex = ew[3 * e + 0];     // coalesced (e sequential)
        const float ey = ew[3 * e + 1];
        const float ez = ew[3 * e + 2];
        int pos = atomicAdd(&g_cursor[i], 1);
        g_rec[pos] = make_float4(ex, ey, ez, __int_as_float(j));
    }
}

// ---------------------------------------------------------------------------
// Kernel 2 (fused): per-node accumulation -- R12 core (458us proven).
// Block = one node, 128 threads.  LDS.64 dup-pair matvec + distance-1 gather
// pipeline.  (distance-2, LDS.128, persistence, carveout all proven slower.)
// Micro-changes vs R12: accumulators seeded with q[i]/mu[i] at block start
// (tail loads eliminated; latency hidden under Wf prologue) and the redundant
// first-chunk barrier skipped.
// ---------------------------------------------------------------------------
#define CHUNK 64
#define RECW  46    // 4 scalars + 20 duplicated pairs (44), padded to even 46

__global__ __launch_bounds__(128)
void node_kernel(const float* __restrict__ q,
                 const float* __restrict__ mu,
                 const float* __restrict__ Wf,
                 const float* __restrict__ bf,
                 float* __restrict__ qout,
                 float* __restrict__ muout)
{
    __shared__ float srec[CHUNK][RECW];   // 11776 B
    __shared__ int   sj[CHUNK];

    const int i = blockIdx.x;
    const int c = threadIdx.x;

    // seed accumulators with the output bases (loads issued early; their
    // latency is covered by the Wf prologue below)
    const float* mi = mu + (size_t)i * F3;
    float aq = q[(size_t)i * FDIM + c];
    float a0 = mi[c];
    float a1 = mi[FDIM + c];
    float a2 = mi[2 * FDIM + c];

    // Wf slices in registers (identical across blocks -> L1-hot broadcast)
    u64   wqr[N_RADIAL];
    float wm[N_RADIAL];
    #pragma unroll
    for (int r = 0; r < N_RADIAL; r++) {
        wqr[r] = pack2(Wf[r * F3 + c], Wf[r * F3 + FDIM + c]);
        wm[r]  = Wf[r * F3 + 2 * FDIM + c];
    }
    const float bq = bf[c], bR = bf[FDIM + c], bm = bf[2 * FDIM + c];

    const int2 range = g_range[i];
    const int beg = range.x;
    const int end = range.y;

    for (int base = beg; base < end; base += CHUNK) {
        const int m = min(CHUNK, end - base);

        if (base != beg) __syncthreads();   // previous chunk fully consumed
        if (c < m) {
            const float4 rec = g_rec[base + c];   // one coalesced LDG.128
            sj[c] = __float_as_int(rec.w);

            const float ex = rec.x;
            const float ey = rec.y;
            const float ez = rec.z;
            const float dd = fmaf(ex, ex, fmaf(ey, ey, ez * ez));
            const float rd = rsqrtf(dd);
            const float d  = dd * rd;

            float s1, c1;
            __sincosf(d * (PI_F / CUTOFF), &s1, &c1);
            float env = 0.5f * (c1 + 1.0f);
            env = (d < CUTOFF) ? env : 0.0f;

            float* row = srec[c];
            row[0] = ex * rd;
            row[1] = ey * rd;
            row[2] = ez * rd;
            row[3] = env;

            const float re    = rd * env;
            const float two_c = 2.0f * c1;
            float sm1 = 0.0f, sn = s1;
            #pragma unroll
            for (int n = 0; n < N_RADIAL; n++) {
                const float b = sn * re;
                *(float2*)&row[4 + 2 * n] = make_float2(b, b);  // dup pair, STS.64
                const float nx = two_c * sn - sm1;
                sm1 = sn; sn = nx;
            }
        }
        __syncthreads();

        // distance-1 software-pipelined gathers (proven R12 form)
        {
            int j0 = sj[0];
            const float* xr = g_x + (size_t)j0 * F3;
            const float* mr = mu  + (size_t)j0 * F3;
            float x0 = xr[c], x1 = xr[FDIM + c], x2 = xr[2 * FDIM + c];
            float m0 = mr[c], m1 = mr[FDIM + c], m2 = mr[2 * FDIM + c];

            #pragma unroll 2
            for (int t = 0; t < m; t++) {
                const int tn = min(t + 1, m - 1);
                const int jn = sj[tn];
                const float* xrn = g_x + (size_t)jn * F3;
                const float* mrn = mu  + (size_t)jn * F3;
                const float nx0 = xrn[c];
                const float nx1 = xrn[FDIM + c];
                const float nx2 = xrn[2 * FDIM + c];
                const float nm0 = mrn[c];
                const float nm1 = mrn[FDIM + c];
                const float nm2 = mrn[2 * FDIM + c];

                const float d0  = srec[t][0];
                const float d1  = srec[t][1];
                const float d2  = srec[t][2];
                const float env = srec[t][3];

                u64   fqr = pack2(bq * env, bR * env);
                float fm  = bm * env;
                #pragma unroll
                for (int r = 0; r < N_RADIAL; r++) {
                    const float2 b2v = *(const float2*)&srec[t][4 + 2 * r];  // LDS.64
                    fma2(fqr, pack2(b2v.x, b2v.y), wqr[r]);
                    fm = fmaf(b2v.x, wm[r], fm);
                }
                float fq, fR; unpack2(fqr, fq, fR);

                aq = fmaf(fq, x0, aq);
                const float dR = fR * x1;
                const float dm = fm * x2;
                a0 = fmaf(dR, d0, fmaf(dm, m0, a0));
                a1 = fmaf(dR, d1, fmaf(dm, m1, a1));
                a2 = fmaf(dR, d2, fmaf(dm, m2, a2));

                x0 = nx0; x1 = nx1; x2 = nx2;
                m0 = nm0; m1 = nm1; m2 = nm2;
            }
        }
    }

    qout[(size_t)i * FDIM + c] = aq;
    float* mo = muout + (size_t)i * F3;
    mo[c]            = a0;
    mo[FDIM + c]     = a1;
    mo[2 * FDIM + c] = a2;
}

// ---------------------------------------------------------------------------
extern "C" void kernel_launch(void* const* d_in, const int* in_sizes, int n_in,
                              void* d_out, int out_size)
{
    const float* q   = (const float*)d_in[0];
    const float* mu  = (const float*)d_in[1];
    const int*   ei  = (const int*)  d_in[2];
    const float* ew  = (const float*)d_in[3];
    const float* W1  = (const float*)d_in[4];
    const float* b1  = (const float*)d_in[5];
    const float* W2  = (const float*)d_in[6];
    const float* b2  = (const float*)d_in[7];
    const float* Wf  = (const float*)d_in[8];
    const float* bf  = (const float*)d_in[9];

    float* out   = (float*)d_out;
    float* qout  = out;                                   // [N, F]
    float* muout = out + (size_t)N_ATOMS * FDIM;          // [N, 3, F]

    float* fx; cudaGetSymbolAddress((void**)&fx, g_x);
    int*   fc; cudaGetSymbolAddress((void**)&fc, g_count);

    // fork: MLP runs on a side stream, concurrent with the CSR chain.
    cudaStream_t s2;
    cudaStreamCreateWithFlags(&s2, cudaStreamNonBlocking);
    cudaEvent_t ev_fork, ev_join;
    cudaEventCreateWithFlags(&ev_fork, cudaEventDisableTiming);
    cudaEventCreateWithFlags(&ev_join, cudaEventDisableTiming);

    cudaEventRecord(ev_fork, 0);
    cudaStreamWaitEvent(s2, ev_fork, 0);
    mlp_kernel<<<N_ATOMS / MROWS, 256, 0, s2>>>(q, W1, b1, W2, b2, fx);
    cudaEventRecord(ev_join, s2);

    // CSR build on the main stream (destination-grouped edge records)
    cudaMemsetAsync(fc, 0, N_ATOMS * sizeof(int), 0);
    hist_kernel<<<N_EDGES / 256, 256>>>(ei);
    scan_kernel<<<1, 1024>>>();
    scatter_kernel<<<N_EDGES / 256, 256>>>(ei, ew);

    // join: node kernel needs both g_x (MLP) and the CSR records
    cudaStreamWaitEvent(0, ev_join, 0);
    node_kernel<<<N_ATOMS, 128>>>(q, mu, Wf, bf, qout, muout);
}

// round 17
// speedup vs baseline: 1.2593x; 1.0116x over previous
#include <cuda_runtime.h>
#include <math.h>

#define N_ATOMS 20000
#define N_EDGES 640000
#define FDIM    128
#define F3      (3 * FDIM)      // 384
#define N_RADIAL 20
#define CUTOFF  5.0f
#define PI_F    3.14159265358979323846f

typedef unsigned long long u64;

// ---------------- scratch (static device globals; no runtime allocs) -------
__device__ float  g_x[(size_t)N_ATOMS * F3];   // node context [N,3F]
__device__ int    g_count[N_ATOMS];
__device__ int2   g_range[N_ATOMS];            // per-node (beg, end)
__device__ int    g_cursor[N_ATOMS];
__device__ float4 g_rec[N_EDGES];              // slot -> (ex, ey, ez, j-as-int)

// ---------------- f32x2 packed helpers -------------------------------------
__device__ __forceinline__ u64 pack2(float x, float y) {
    u64 r; asm("mov.b64 %0, {%1,%2};" : "=l"(r) : "f"(x), "f"(y)); return r;
}
__device__ __forceinline__ void unpack2(u64 v, float& x, float& y) {
    asm("mov.b64 {%0,%1}, %2;" : "=f"(x), "=f"(y) : "l"(v));
}
__device__ __forceinline__ void fma2(u64& d, u64 a, u64 b) {
    asm("fma.rn.f32x2 %0, %1, %2, %0;" : "+l"(d) : "l"(a), "l"(b));
}

// ---------------------------------------------------------------------------
// Kernel 1: node MLP, scalar FFMA, LDS.128 k-unroll, 16 rows / 256 threads,
// register double-buffered weight prefetch (measured ~106us).
// NOTE: no cache-carveout attributes -- per-kernel carveout switching inside
// a captured graph forces SM reconfiguration per replay (R15: +106us).
// ---------------------------------------------------------------------------
#define MROWS 16

__global__ __launch_bounds__(256)
void mlp_kernel(const float* __restrict__ q,
                const float* __restrict__ W1, const float* __restrict__ b1,
                const float* __restrict__ W2, const float* __restrict__ b2,
                float* __restrict__ x)
{
    __shared__ float qs[MROWS][FDIM];   // 8 KB, k fastest (float4-able)
    __shared__ float hs[MROWS][FDIM];   // 8 KB

    const int f    = threadIdx.x & 127;
    const int half = threadIdx.x >> 7;       // 0/1
    const int r0   = half * 8;                // local row base (8 rows/half)
    const int row0 = blockIdx.x * MROWS;

    for (int idx = threadIdx.x; idx < MROWS * FDIM; idx += 256)
        qs[idx >> 7][idx & 127] = q[(size_t)row0 * FDIM + idx];
    __syncthreads();

    // stage 1: h = silu(q @ W1 + b1)
    {
        float acc[8];
        const float bb = b1[f];
        #pragma unroll
        for (int r = 0; r < 8; r++) acc[r] = bb;

        float w0 = W1[0 * FDIM + f];
        float w1 = W1[1 * FDIM + f];
        float w2 = W1[2 * FDIM + f];
        float w3 = W1[3 * FDIM + f];

        for (int k = 0; k < FDIM; k += 4) {
            const int kn = (k + 4) & (FDIM - 1);   // wraps to 0 on last tile
            const float n0 = W1[(kn + 0) * FDIM + f];
            const float n1 = W1[(kn + 1) * FDIM + f];
            const float n2 = W1[(kn + 2) * FDIM + f];
            const float n3 = W1[(kn + 3) * FDIM + f];
            #pragma unroll
            for (int r = 0; r < 8; r++) {
                const float4 qv = *(const float4*)&qs[r0 + r][k];  // LDS.128 bcast
                acc[r] = fmaf(qv.x, w0, acc[r]);
                acc[r] = fmaf(qv.y, w1, acc[r]);
                acc[r] = fmaf(qv.z, w2, acc[r]);
                acc[r] = fmaf(qv.w, w3, acc[r]);
            }
            w0 = n0; w1 = n1; w2 = n2; w3 = n3;
        }
        #pragma unroll
        for (int r = 0; r < 8; r++) {
            const float v = acc[r];
            hs[r0 + r][f] = v / (1.0f + __expf(-v));
        }
    }
    __syncthreads();

    // stage 2: x = h @ W2 + b2
    {
        float a0[8], a1[8], a2[8];
        const float c0 = b2[f], c1 = b2[FDIM + f], c2 = b2[2 * FDIM + f];
        #pragma unroll
        for (int r = 0; r < 8; r++) { a0[r] = c0; a1[r] = c1; a2[r] = c2; }

        float wa[4], wb[4], wc[4];
        #pragma unroll
        for (int u = 0; u < 4; u++) {
            wa[u] = W2[u * F3 + f];
            wb[u] = W2[u * F3 + FDIM + f];
            wc[u] = W2[u * F3 + 2 * FDIM + f];
        }

        for (int k = 0; k < FDIM; k += 4) {
            const int kn = (k + 4) & (FDIM - 1);   // wraps to 0 on last tile
            float na[4], nb[4], nc[4];
            #pragma unroll
            for (int u = 0; u < 4; u++) {
                na[u] = W2[(kn + u) * F3 + f];
                nb[u] = W2[(kn + u) * F3 + FDIM + f];
                nc[u] = W2[(kn + u) * F3 + 2 * FDIM + f];
            }
            #pragma unroll
            for (int r = 0; r < 8; r++) {
                const float4 hv = *(const float4*)&hs[r0 + r][k];  // LDS.128 bcast
                a0[r] = fmaf(hv.x, wa[0], a0[r]);
                a0[r] = fmaf(hv.y, wa[1], a0[r]);
                a0[r] = fmaf(hv.z, wa[2], a0[r]);
                a0[r] = fmaf(hv.w, wa[3], a0[r]);
                a1[r] = fmaf(hv.x, wb[0], a1[r]);
                a1[r] = fmaf(hv.y, wb[1], a1[r]);
                a1[r] = fmaf(hv.z, wb[2], a1[r]);
                a1[r] = fmaf(hv.w, wb[3], a1[r]);
                a2[r] = fmaf(hv.x, wc[0], a2[r]);
                a2[r] = fmaf(hv.y, wc[1], a2[r]);
                a2[r] = fmaf(hv.z, wc[2], a2[r]);
                a2[r] = fmaf(hv.w, wc[3], a2[r]);
            }
            #pragma unroll
            for (int u = 0; u < 4; u++) { wa[u] = na[u]; wb[u] = nb[u]; wc[u] = nc[u]; }
        }
        #pragma unroll
        for (int r = 0; r < 8; r++) {
            const size_t base = (size_t)(row0 + r0 + r) * F3;
            x[base + f]            = a0[r];
            x[base + FDIM + f]     = a1[r];
            x[base + 2 * FDIM + f] = a2[r];
        }
    }
}

// ---------------------------------------------------------------------------
// CSR construction: memset -> histogram -> scan -> scatter (float4 records)
// ---------------------------------------------------------------------------
__global__ void hist_kernel(const int* __restrict__ edge_index)
{
    int e = blockIdx.x * blockDim.x + threadIdx.x;
    if (e < N_EDGES) atomicAdd(&g_count[edge_index[e]], 1);
}

__global__ __launch_bounds__(1024)
void scan_kernel()
{
    __shared__ int warp_sums[32];
    __shared__ int chunk_carry;
    const int tid  = threadIdx.x;
    const int lane = tid & 31;
    const int wid  = tid >> 5;
    if (tid == 0) chunk_carry = 0;
    __syncthreads();

    const int nchunks = (N_ATOMS + 1023) / 1024;
    for (int c = 0; c < nchunks; c++) {
        int idx = c * 1024 + tid;
        int v = (idx < N_ATOMS) ? g_count[idx] : 0;
        int s = v;
        #pragma unroll
        for (int o = 1; o < 32; o <<= 1) {
            int t = __shfl_up_sync(0xffffffffu, s, o);
            if (lane >= o) s += t;
        }
        if (lane == 31) warp_sums[wid] = s;
        __syncthreads();
        if (wid == 0) {
            int ws = warp_sums[lane];
            #pragma unroll
            for (int o = 1; o < 32; o <<= 1) {
                int t = __shfl_up_sync(0xffffffffu, ws, o);
                if (lane >= o) ws += t;
            }
            warp_sums[lane] = ws;
        }
        __syncthreads();
        int warp_off = (wid > 0) ? warp_sums[wid - 1] : 0;
        int excl = chunk_carry + warp_off + s - v;
        if (idx < N_ATOMS) {
            g_range[idx]  = make_int2(excl, excl + v);   // (beg, end)
            g_cursor[idx] = excl;
        }
        __syncthreads();
        if (tid == 1023) chunk_carry += warp_off + s;
    }
}

// writes a self-contained 16B record per edge: (ex, ey, ez, j)
__global__ void scatter_kernel(const int* __restrict__ edge_index,
                               const float* __restrict__ ew)
{
    int e = blockIdx.x * blockDim.x + threadIdx.x;
    if (e < N_EDGES) {
        const int i = edge_index[e];
        const int j = edge_index[N_EDGES + e];
        const float ex = ew[3 * e + 0];     // coalesced (e sequential)
        const float ey = ew[3 * e + 1];
        const float ez = ew[3 * e + 2];
        int pos = atomicAdd(&g_cursor[i], 1);
        g_rec[pos] = make_float4(ex, ey, ez, __int_as_float(j));
    }
}

// ---------------------------------------------------------------------------
// Kernel 2 (fused): per-node accumulation -- R16 core (453us proven).
// Block = one node, 128 threads.  LDS.64 dup-pair matvec + distance-1 gather
// pipeline; accumulators seeded with q[i]/mu[i] at block start.
// CHANGE vs R16: the staged basis pair is loaded directly as u64 and fed to
// fma2 (no float2 unpack -> pack2 repack); the fm chain reads the low float
// via a dead-high unpack (register alias).  Same loads, same math, fewer MOVs.
// ---------------------------------------------------------------------------
#define CHUNK 64
#define RECW  46    // 4 scalars + 20 duplicated pairs (44), padded to even 46

__global__ __launch_bounds__(128)
void node_kernel(const float* __restrict__ q,
                 const float* __restrict__ mu,
                 const float* __restrict__ Wf,
                 const float* __restrict__ bf,
                 float* __restrict__ qout,
                 float* __restrict__ muout)
{
    __shared__ float srec[CHUNK][RECW];   // 11776 B
    __shared__ int   sj[CHUNK];

    const int i = blockIdx.x;
    const int c = threadIdx.x;

    // seed accumulators with the output bases (loads issued early; their
    // latency is covered by the Wf prologue below)
    const float* mi = mu + (size_t)i * F3;
    float aq = q[(size_t)i * FDIM + c];
    float a0 = mi[c];
    float a1 = mi[FDIM + c];
    float a2 = mi[2 * FDIM + c];

    // Wf slices in registers (identical across blocks -> L1-hot broadcast)
    u64   wqr[N_RADIAL];
    float wm[N_RADIAL];
    #pragma unroll
    for (int r = 0; r < N_RADIAL; r++) {
        wqr[r] = pack2(Wf[r * F3 + c], Wf[r * F3 + FDIM + c]);
        wm[r]  = Wf[r * F3 + 2 * FDIM + c];
    }
    const float bq = bf[c], bR = bf[FDIM + c], bm = bf[2 * FDIM + c];

    const int2 range = g_range[i];
    const int beg = range.x;
    const int end = range.y;

    for (int base = beg; base < end; base += CHUNK) {
        const int m = min(CHUNK, end - base);

        if (base != beg) __syncthreads();   // previous chunk fully consumed
        if (c < m) {
            const float4 rec = g_rec[base + c];   // one coalesced LDG.128
            sj[c] = __float_as_int(rec.w);

            const float ex = rec.x;
            const float ey = rec.y;
            const float ez = rec.z;
            const float dd = fmaf(ex, ex, fmaf(ey, ey, ez * ez));
            const float rd = rsqrtf(dd);
            const float d  = dd * rd;

            float s1, c1;
            __sincosf(d * (PI_F / CUTOFF), &s1, &c1);
            float env = 0.5f * (c1 + 1.0f);
            env = (d < CUTOFF) ? env : 0.0f;

            float* row = srec[c];
            row[0] = ex * rd;
            row[1] = ey * rd;
            row[2] = ez * rd;
            row[3] = env;

            const float re    = rd * env;
            const float two_c = 2.0f * c1;
            float sm1 = 0.0f, sn = s1;
            #pragma unroll
            for (int n = 0; n < N_RADIAL; n++) {
                const float b = sn * re;
                *(float2*)&row[4 + 2 * n] = make_float2(b, b);  // dup pair, STS.64
                const float nx = two_c * sn - sm1;
                sm1 = sn; sn = nx;
            }
        }
        __syncthreads();

        // distance-1 software-pipelined gathers (proven R12 form)
        {
            int j0 = sj[0];
            const float* xr = g_x + (size_t)j0 * F3;
            const float* mr = mu  + (size_t)j0 * F3;
            float x0 = xr[c], x1 = xr[FDIM + c], x2 = xr[2 * FDIM + c];
            float m0 = mr[c], m1 = mr[FDIM + c], m2 = mr[2 * FDIM + c];

            #pragma unroll 2
            for (int t = 0; t < m; t++) {
                const int tn = min(t + 1, m - 1);
                const int jn = sj[tn];
                const float* xrn = g_x + (size_t)jn * F3;
                const float* mrn = mu  + (size_t)jn * F3;
                const float nx0 = xrn[c];
                const float nx1 = xrn[FDIM + c];
                const float nx2 = xrn[2 * FDIM + c];
                const float nm0 = mrn[c];
                const float nm1 = mrn[FDIM + c];
                const float nm2 = mrn[2 * FDIM + c];

                const float d0  = srec[t][0];
                const float d1  = srec[t][1];
                const float d2  = srec[t][2];
                const float env = srec[t][3];

                u64   fqr = pack2(bq * env, bR * env);
                float fm  = bm * env;
                #pragma unroll
                for (int r = 0; r < N_RADIAL; r++) {
                    // LDS.64 straight into the packed FMA -- no repack
                    const u64 bb = *(const u64*)&srec[t][4 + 2 * r];
                    fma2(fqr, bb, wqr[r]);
                    float bx, by_dead;
                    unpack2(bb, bx, by_dead);      // register alias; by_dead unused
                    fm = fmaf(bx, wm[r], fm);
                }
                float fq, fR; unpack2(fqr, fq, fR);

                aq = fmaf(fq, x0, aq);
                const float dR = fR * x1;
                const float dm = fm * x2;
                a0 = fmaf(dR, d0, fmaf(dm, m0, a0));
                a1 = fmaf(dR, d1, fmaf(dm, m1, a1));
                a2 = fmaf(dR, d2, fmaf(dm, m2, a2));

                x0 = nx0; x1 = nx1; x2 = nx2;
                m0 = nm0; m1 = nm1; m2 = nm2;
            }
        }
    }

    qout[(size_t)i * FDIM + c] = aq;
    float* mo = muout + (size_t)i * F3;
    mo[c]            = a0;
    mo[FDIM + c]     = a1;
    mo[2 * FDIM + c] = a2;
}

// ---------------------------------------------------------------------------
extern "C" void kernel_launch(void* const* d_in, const int* in_sizes, int n_in,
                              void* d_out, int out_size)
{
    const float* q   = (const float*)d_in[0];
    const float* mu  = (const float*)d_in[1];
    const int*   ei  = (const int*)  d_in[2];
    const float* ew  = (const float*)d_in[3];
    const float* W1  = (const float*)d_in[4];
    const float* b1  = (const float*)d_in[5];
    const float* W2  = (const float*)d_in[6];
    const float* b2  = (const float*)d_in[7];
    const float* Wf  = (const float*)d_in[8];
    const float* bf  = (const float*)d_in[9];

    float* out   = (float*)d_out;
    float* qout  = out;                                   // [N, F]
    float* muout = out + (size_t)N_ATOMS * FDIM;          // [N, 3, F]

    float* fx; cudaGetSymbolAddress((void**)&fx, g_x);
    int*   fc; cudaGetSymbolAddress((void**)&fc, g_count);

    // fork: MLP runs on a side stream, concurrent with the CSR chain.
    cudaStream_t s2;
    cudaStreamCreateWithFlags(&s2, cudaStreamNonBlocking);
    cudaEvent_t ev_fork, ev_join;
    cudaEventCreateWithFlags(&ev_fork, cudaEventDisableTiming);
    cudaEventCreateWithFlags(&ev_join, cudaEventDisableTiming);

    cudaEventRecord(ev_fork, 0);
    cudaStreamWaitEvent(s2, ev_fork, 0);
    mlp_kernel<<<N_ATOMS / MROWS, 256, 0, s2>>>(q, W1, b1, W2, b2, fx);
    cudaEventRecord(ev_join, s2);

    // CSR build on the main stream (destination-grouped edge records)
    cudaMemsetAsync(fc, 0, N_ATOMS * sizeof(int), 0);
    hist_kernel<<<N_EDGES / 256, 256>>>(ei);
    scan_kernel<<<1, 1024>>>();
    scatter_kernel<<<N_EDGES / 256, 256>>>(ei, ew);

    // join: node kernel needs both g_x (MLP) and the CSR records
    cudaStreamWaitEvent(0, ev_join, 0);
    node_kernel<<<N_ATOMS, 128>>>(q, mu, Wf, bf, qout, muout);
}